// round 7
// baseline (speedup 1.0000x reference)
#include <cuda_runtime.h>
#include <cuda_bf16.h>
#include <cstdint>

#define CONST __restrict__
using bf16 = __nv_bfloat16;

static constexpr int B_  = 1024;
static constexpr int KO  = 10;
static constexpr int D_  = 32;
static constexpr int H_  = 512;
static constexpr int NN  = B_ * KO;     // 10240
static constexpr int EPN = KO - 1;      // 9
static constexpr int NE  = NN * EPN;    // 92160
static constexpr float EPS = 1e-5f;
static constexpr int K4  = 544;

static constexpr int NSLICE = 4;
static constexpr int ESL = NE / NSLICE;
static constexpr int NSL = NN / NSLICE;

// ---------------- scratch planes ----------------
__device__ __align__(16) bf16 gSTh[NN * D_],  gSTl[NN * D_];
__device__ __align__(16) bf16 gPh [NN * H_],  gPl [NN * H_];
__device__ __align__(16) bf16 gQh [NN * H_],  gQl [NN * H_];
__device__ __align__(16) bf16 gEh [(size_t)NE * H_], gEl[(size_t)NE * H_];
__device__ float gH2 [(size_t)NE * H_];
__device__ __align__(16) bf16 gSh [NN * H_],  gSl [NN * H_];
__device__ __align__(16) bf16 gA4h[NN * K4],  gA4l[NN * K4];
__device__ __align__(16) bf16 gN1h[NN * H_],  gN1l[NN * H_];
__device__ float gN2r[NN * H_], gN2[NN * H_];

// split transposed weights [N][K]
__device__ __align__(16) bf16 gW0h[H_ * 32],  gW0l[H_ * 32];
__device__ __align__(16) bf16 gW1h[H_ * 32],  gW1l[H_ * 32];
__device__ __align__(16) bf16 gW2h[H_ * H_],  gW2l[H_ * H_];
__device__ __align__(16) bf16 gW3h[H_ * H_],  gW3l[H_ * H_];
__device__ __align__(16) bf16 gW4h[H_ * K4],  gW4l[H_ * K4];
__device__ __align__(16) bf16 gW5h[H_ * H_],  gW5l[H_ * H_];

// ---------------- helpers ----------------
__device__ __forceinline__ uint32_t s2u(const void* p) {
    uint32_t a;
    asm("{ .reg .u64 t; cvta.to.shared.u64 t, %1; cvt.u32.u64 %0, t; }" : "=r"(a) : "l"(p));
    return a;
}
__device__ __forceinline__ void cp16(uint32_t s, const void* g) {
    asm volatile("cp.async.cg.shared.global [%0], [%1], 16;" :: "r"(s), "l"(g));
}
__device__ __forceinline__ void ldsm4(uint32_t* r, uint32_t a) {
    asm volatile("ldmatrix.sync.aligned.m8n8.x4.shared.b16 {%0,%1,%2,%3}, [%4];"
        : "=r"(r[0]), "=r"(r[1]), "=r"(r[2]), "=r"(r[3]) : "r"(a));
}
__device__ __forceinline__ void ldsm2(uint32_t& r0, uint32_t& r1, uint32_t a) {
    asm volatile("ldmatrix.sync.aligned.m8n8.x2.shared.b16 {%0,%1}, [%2];"
        : "=r"(r0), "=r"(r1) : "r"(a));
}
// NOTE: non-volatile — lets ptxas schedule MMAs freely between ldmatrix ops.
__device__ __forceinline__ void mma_bf16(float* c, const uint32_t* a, uint32_t b0, uint32_t b1) {
    asm("mma.sync.aligned.m16n8k16.row.col.f32.bf16.bf16.f32 "
        "{%0,%1,%2,%3}, {%4,%5,%6,%7}, {%8,%9}, {%0,%1,%2,%3};\n"
        : "+f"(c[0]), "+f"(c[1]), "+f"(c[2]), "+f"(c[3])
        : "r"(a[0]), "r"(a[1]), "r"(a[2]), "r"(a[3]), "r"(b0), "r"(b1));
}
__device__ __forceinline__ uint32_t pk(bf16 a, bf16 b) {
    __nv_bfloat162 t; t.x = a; t.y = b; return *(uint32_t*)&t;
}
__device__ __forceinline__ void splitpack(float v0, float v1, uint32_t& h, uint32_t& l) {
    bf16 h0 = __float2bfloat16(v0), h1 = __float2bfloat16(v1);
    bf16 l0 = __float2bfloat16(v0 - __bfloat162float(h0));
    bf16 l1 = __float2bfloat16(v1 - __bfloat162float(h1));
    h = pk(h0, h1); l = pk(l0, l1);
}

// ---------------- single merged weight-prep kernel ----------------
__global__ void prep_all(const float* CONST ew1, const float* CONST ew2,
                         const float* CONST ew3, const float* CONST nw1,
                         const float* CONST nw2)
{
    int idx = blockIdx.x * 256 + threadIdx.x;
    if (idx >= 1097728) return;
    const float* src; bf16 *dh, *dl; int K, off, skip = 0;
    if      (idx < 16384)  { src = ew1;            dh = gW0h; dl = gW0l; K = 32;  off = 0; }
    else if (idx < 32768)  { src = ew1 + 32 * H_;  dh = gW1h; dl = gW1l; K = 32;  off = 16384; }
    else if (idx < 294912) { src = ew2;            dh = gW2h; dl = gW2l; K = 512; off = 32768; }
    else if (idx < 557056) { src = ew3;            dh = gW3h; dl = gW3l; K = 512; off = 294912; }
    else if (idx < 835584) { src = nw1;            dh = gW4h; dl = gW4l; K = K4;  off = 557056; skip = 1; }
    else                   { src = nw2;            dh = gW5h; dl = gW5l; K = 512; off = 835584; }
    idx -= off;
    int k = idx % K, n = idx / K;
    int sr = (skip && k >= 32) ? k + 4 : k;
    float v = src[(size_t)sr * H_ + n];
    bf16 h = __float2bfloat16(v);
    dh[idx] = h;
    dl[idx] = __float2bfloat16(v - __bfloat162float(h));
}

__global__ void prep_states(const float* CONST s)
{
    int idx = blockIdx.x * 256 + threadIdx.x;
    if (idx >= NN * D_) return;
    float v = s[idx];
    bf16 h = __float2bfloat16(v);
    bf16 l = __float2bfloat16(v - __bfloat162float(h));
    gSTh[idx] = h; gSTl[idx] = l;
    int r = idx >> 5, c = idx & 31;
    gA4h[r * K4 + c] = h;
    gA4l[r * K4 + c] = l;
}

// ---------------- edge A materialization: relu(P+Q) split ----------------
__global__ __launch_bounds__(256) void esplit(int edgeOff)
{
    int gi = blockIdx.x * 256 + threadIdx.x;
    int e = edgeOff + (gi >> 6);
    int cg = (gi & 63) * 8;
    int node = e / EPN;
    int jj = e - node * EPN;
    int i = node % KO;
    int j = jj + (jj >= i ? 1 : 0);
    int cn = node - i + j;

    bf16 a[8], b[8], c2[8], d2[8], oh[8], ol[8];
    *(uint4*)a  = *(const uint4*)(gPh + (size_t)node * H_ + cg);
    *(uint4*)b  = *(const uint4*)(gPl + (size_t)node * H_ + cg);
    *(uint4*)c2 = *(const uint4*)(gQh + (size_t)cn * H_ + cg);
    *(uint4*)d2 = *(const uint4*)(gQl + (size_t)cn * H_ + cg);
    #pragma unroll
    for (int u = 0; u < 8; u++) {
        float v = (__bfloat162float(a[u]) + __bfloat162float(b[u]))
                + (__bfloat162float(c2[u]) + __bfloat162float(d2[u]));
        v = fmaxf(v, 0.f);
        oh[u] = __float2bfloat16(v);
        ol[u] = __float2bfloat16(v - __bfloat162float(oh[u]));
    }
    *(uint4*)(gEh + (size_t)e * H_ + cg) = *(const uint4*)oh;
    *(uint4*)(gEl + (size_t)e * H_ + cg) = *(const uint4*)ol;
}

// ---------------- cp.async double-buffered split-bf16 mma GEMM ----------------
static constexpr int LDP = 40;
static constexpr int SZA = 128 * LDP * 2;        // 10240 B per array
static constexpr int STG = 4 * SZA;              // 40960 B per stage
static constexpr int SMEM_SZ = 2 * STG;          // 81920 B

template <int MODE>
__global__ __launch_bounds__(256, 2)
void tg(const bf16* CONST Ah_, const bf16* CONST Al_,
        const bf16* CONST Bh_, const bf16* CONST Bl_,
        const float* CONST bias, const int* CONST act,
        const float* CONST nw1full, int rowOff)
{
    constexpr int KT = (MODE <= 1) ? 32 : (MODE == 4 ? K4 : 512);
    constexpr int NC = KT / 32;
    extern __shared__ char smraw[];
    const uint32_t sbase = s2u(smraw);

    const int tid = threadIdx.x, warp = tid >> 5, lane = tid & 31;
    const int rowBase = rowOff + blockIdx.y * 128;
    const int colBase = blockIdx.x * 128;
    const int fr = tid >> 1, fks = (tid & 1) * 16;

    const bf16* pAh = Ah_ + (size_t)(rowBase + fr) * KT + fks;
    const bf16* pAl = Al_ + (size_t)(rowBase + fr) * KT + fks;
    const bf16* pBh = Bh_ + (size_t)(colBase + fr) * KT + fks;
    const bf16* pBl = Bl_ + (size_t)(colBase + fr) * KT + fks;

    const uint32_t wb = sbase + (fr * LDP + fks) * 2;
    auto ldgsts = [&](int stg, int k0) {
        const uint32_t d = wb + stg * STG;
        cp16(d,                pAh + k0);  cp16(d + 16,            pAh + k0 + 8);
        cp16(d + SZA,          pAl + k0);  cp16(d + SZA + 16,      pAl + k0 + 8);
        cp16(d + 2 * SZA,      pBh + k0);  cp16(d + 2 * SZA + 16,  pBh + k0 + 8);
        cp16(d + 3 * SZA,      pBl + k0);  cp16(d + 3 * SZA + 16,  pBl + k0 + 8);
        asm volatile("cp.async.commit_group;");
    };

    const int wm = warp >> 2, wn = warp & 3;     // 2x4 warps, tile 64x32
    const int la_row = lane & 15, la_sel = lane >> 4;
    const int lb_row = lane & 7,  lb_sel = (lane >> 3) & 1;

    float acc[4][4][4];
    #pragma unroll
    for (int a = 0; a < 4; a++)
        #pragma unroll
        for (int b = 0; b < 4; b++)
            #pragma unroll
            for (int c = 0; c < 4; c++) acc[a][b][c] = 0.f;

    ldgsts(0, 0);
    for (int c = 0; c < NC; c++) {
        if (c + 1 < NC) {
            ldgsts((c + 1) & 1, (c + 1) * 32);
            asm volatile("cp.async.wait_group 1;");
        } else {
            asm volatile("cp.async.wait_group 0;");
        }
        __syncthreads();

        const uint32_t uA = sbase + (c & 1) * STG;
        const uint32_t uB = uA + 2 * SZA;
        #pragma unroll
        for (int kf = 0; kf < 2; kf++) {
            const int kb = kf * 16;
            uint32_t ah[4][4], al[4][4];
            #pragma unroll
            for (int mt = 0; mt < 4; mt++) {
                const uint32_t ra =
                    (uint32_t)(((wm * 64 + mt * 16 + la_row) * LDP + kb + la_sel * 8) * 2);
                ldsm4(ah[mt], uA + ra);
                ldsm4(al[mt], uA + SZA + ra);
            }
            #pragma unroll
            for (int nt = 0; nt < 4; nt++) {
                const uint32_t rb =
                    (uint32_t)(((wn * 32 + nt * 8 + lb_row) * LDP + kb + lb_sel * 8) * 2);
                uint32_t bh0, bh1, bl0, bl1;
                ldsm2(bh0, bh1, uB + rb);
                ldsm2(bl0, bl1, uB + SZA + rb);
                // Issue order: same-accumulator reuse distance = 4 MMAs,
                // so each issue sees only throughput (rt), never latency.
                #pragma unroll
                for (int mt = 0; mt < 4; mt++)
                    mma_bf16(acc[mt][nt], ah[mt], bh0, bh1);
                #pragma unroll
                for (int mt = 0; mt < 4; mt++)
                    mma_bf16(acc[mt][nt], ah[mt], bl0, bl1);
                #pragma unroll
                for (int mt = 0; mt < 4; mt++)
                    mma_bf16(acc[mt][nt], al[mt], bh0, bh1);
            }
        }
        __syncthreads();
    }

    // ---- epilogue ----
    const int g = lane >> 2, tg2 = (lane & 3) * 2;
    #pragma unroll
    for (int mt = 0; mt < 4; mt++) {
        const int row0 = rowBase + wm * 64 + mt * 16 + g;
        const int row1 = row0 + 8;
        int a0r = 0, a1r = 0;
        if constexpr (MODE == 4) { a0r = act[row0 / KO]; a1r = act[row1 / KO]; }
        #pragma unroll
        for (int nt = 0; nt < 4; nt++) {
            const int col = colBase + wn * 32 + nt * 8 + tg2;
            float v0 = acc[mt][nt][0], v1 = acc[mt][nt][1];
            float v2 = acc[mt][nt][2], v3 = acc[mt][nt][3];
            if constexpr (MODE == 0 || MODE == 2 || MODE == 5) {
                float b0 = bias[col], b1 = bias[col + 1];
                v0 += b0; v1 += b1; v2 += b0; v3 += b1;
            }
            if constexpr (MODE == 3) {
                float b0 = 9.f * bias[col], b1 = 9.f * bias[col + 1];
                v0 += b0; v1 += b1; v2 += b0; v3 += b1;
            }
            if constexpr (MODE == 4) {
                float b0 = bias[col], b1 = bias[col + 1];
                const float* r0p = nw1full + (size_t)(32 + a0r) * H_;
                const float* r1p = nw1full + (size_t)(32 + a1r) * H_;
                v0 = fmaxf(v0 + b0 + r0p[col],     0.f);
                v1 = fmaxf(v1 + b1 + r0p[col + 1], 0.f);
                v2 = fmaxf(v2 + b0 + r1p[col],     0.f);
                v3 = fmaxf(v3 + b1 + r1p[col + 1], 0.f);
            }
            if constexpr (MODE == 2) {
                *(float2*)(gH2 + (size_t)row0 * H_ + col) = make_float2(v0, v1);
                *(float2*)(gH2 + (size_t)row1 * H_ + col) = make_float2(v2, v3);
            } else if constexpr (MODE == 5) {
                *(float2*)(gN2r + (size_t)row0 * H_ + col) = make_float2(v0, v1);
                *(float2*)(gN2r + (size_t)row1 * H_ + col) = make_float2(v2, v3);
            } else {
                uint32_t h01, l01, h23, l23;
                splitpack(v0, v1, h01, l01);
                splitpack(v2, v3, h23, l23);
                if constexpr (MODE == 0) {
                    *(uint32_t*)(gPh + (size_t)row0 * H_ + col) = h01;
                    *(uint32_t*)(gPl + (size_t)row0 * H_ + col) = l01;
                    *(uint32_t*)(gPh + (size_t)row1 * H_ + col) = h23;
                    *(uint32_t*)(gPl + (size_t)row1 * H_ + col) = l23;
                } else if constexpr (MODE == 1) {
                    *(uint32_t*)(gQh + (size_t)row0 * H_ + col) = h01;
                    *(uint32_t*)(gQl + (size_t)row0 * H_ + col) = l01;
                    *(uint32_t*)(gQh + (size_t)row1 * H_ + col) = h23;
                    *(uint32_t*)(gQl + (size_t)row1 * H_ + col) = l23;
                } else if constexpr (MODE == 3) {
                    *(uint32_t*)(gA4h + (size_t)row0 * K4 + 32 + col) = h01;
                    *(uint32_t*)(gA4l + (size_t)row0 * K4 + 32 + col) = l01;
                    *(uint32_t*)(gA4h + (size_t)row1 * K4 + 32 + col) = h23;
                    *(uint32_t*)(gA4l + (size_t)row1 * K4 + 32 + col) = l23;
                } else {
                    *(uint32_t*)(gN1h + (size_t)row0 * H_ + col) = h01;
                    *(uint32_t*)(gN1l + (size_t)row0 * H_ + col) = l01;
                    *(uint32_t*)(gN1h + (size_t)row1 * H_ + col) = h23;
                    *(uint32_t*)(gN1l + (size_t)row1 * H_ + col) = l23;
                }
            }
        }
    }
}

// ---------------- LN + relu + 9-row sum -> split S planes ----------------
__global__ __launch_bounds__(256)
void ln_sum_k(const float* CONST g, const float* CONST bt, int nodeOff)
{
    const int tid = threadIdx.x, warp = tid >> 5, lane = tid & 31;
    const int n = nodeOff + blockIdx.x * 8 + warp;
    const float4* gg = (const float4*)g;
    const float4* bb = (const float4*)bt;
    float4 G[4], Bt[4], acc[4];
    #pragma unroll
    for (int j = 0; j < 4; j++) {
        G[j] = gg[lane + 32 * j];
        Bt[j] = bb[lane + 32 * j];
        acc[j] = make_float4(0.f, 0.f, 0.f, 0.f);
    }
    for (int e = 0; e < EPN; e++) {
        const float4* rp = (const float4*)(gH2 + (size_t)(n * EPN + e) * H_);
        float4 v[4];
        float s = 0.f, sq = 0.f;
        #pragma unroll
        for (int j = 0; j < 4; j++) {
            v[j] = rp[lane + 32 * j];
            s  += v[j].x + v[j].y + v[j].z + v[j].w;
            sq += v[j].x * v[j].x + v[j].y * v[j].y + v[j].z * v[j].z + v[j].w * v[j].w;
        }
        #pragma unroll
        for (int o = 16; o > 0; o >>= 1) {
            s  += __shfl_xor_sync(0xffffffff, s, o);
            sq += __shfl_xor_sync(0xffffffff, sq, o);
        }
        const float mean = s * (1.f / 512.f);
        const float rstd = rsqrtf(sq * (1.f / 512.f) - mean * mean + EPS);
        #pragma unroll
        for (int j = 0; j < 4; j++) {
            acc[j].x += fmaxf((v[j].x - mean) * rstd * G[j].x + Bt[j].x, 0.f);
            acc[j].y += fmaxf((v[j].y - mean) * rstd * G[j].y + Bt[j].y, 0.f);
            acc[j].z += fmaxf((v[j].z - mean) * rstd * G[j].z + Bt[j].z, 0.f);
            acc[j].w += fmaxf((v[j].w - mean) * rstd * G[j].w + Bt[j].w, 0.f);
        }
    }
    #pragma unroll
    for (int j = 0; j < 4; j++) {
        const int cb = (lane + 32 * j) * 4;
        uint32_t h01, l01, h23, l23;
        splitpack(acc[j].x, acc[j].y, h01, l01);
        splitpack(acc[j].z, acc[j].w, h23, l23);
        *(uint2*)(gSh + (size_t)n * H_ + cb) = make_uint2(h01, h23);
        *(uint2*)(gSl + (size_t)n * H_ + cb) = make_uint2(l01, l23);
    }
}

// ---------------- LN + relu of gN2r ----------------
__global__ __launch_bounds__(256)
void ln2_k(const float* CONST g, const float* CONST bt)
{
    const int tid = threadIdx.x, warp = tid >> 5, lane = tid & 31;
    const int n = blockIdx.x * 8 + warp;
    const float4* rp = (const float4*)(gN2r + (size_t)n * H_);
    float4 v[4];
    float s = 0.f, sq = 0.f;
    #pragma unroll
    for (int j = 0; j < 4; j++) {
        v[j] = rp[lane + 32 * j];
        s  += v[j].x + v[j].y + v[j].z + v[j].w;
        sq += v[j].x * v[j].x + v[j].y * v[j].y + v[j].z * v[j].z + v[j].w * v[j].w;
    }
    #pragma unroll
    for (int o = 16; o > 0; o >>= 1) {
        s  += __shfl_xor_sync(0xffffffff, s, o);
        sq += __shfl_xor_sync(0xffffffff, sq, o);
    }
    const float mean = s * (1.f / 512.f);
    const float rstd = rsqrtf(sq * (1.f / 512.f) - mean * mean + EPS);
    float4* op = (float4*)(gN2 + (size_t)n * H_);
    #pragma unroll
    for (int j = 0; j < 4; j++) {
        const int c = (lane + 32 * j) * 4;
        float4 o4;
        o4.x = fmaxf((v[j].x - mean) * rstd * g[c]     + bt[c],     0.f);
        o4.y = fmaxf((v[j].y - mean) * rstd * g[c + 1] + bt[c + 1], 0.f);
        o4.z = fmaxf((v[j].z - mean) * rstd * g[c + 2] + bt[c + 2], 0.f);
        o4.w = fmaxf((v[j].w - mean) * rstd * g[c + 3] + bt[c + 3], 0.f);
        op[lane + 32 * j] = o4;
    }
}

// ---------------- out = gN2 @ nw3 + nb3 ----------------
__global__ __launch_bounds__(256)
void n3_k(const float* CONST w3, const float* CONST b3, float* CONST out)
{
    __shared__ float xs[8][H_];
    const int r0 = blockIdx.x * 8;
    const int t = threadIdx.x;
    for (int i = t; i < 8 * H_; i += 256)
        xs[i >> 9][i & 511] = gN2[(size_t)(r0 + (i >> 9)) * H_ + (i & 511)];
    __syncthreads();
    const int lr = t >> 5, c = t & 31;
    float accv = b3[c];
    #pragma unroll 8
    for (int k = 0; k < H_; k++)
        accv = fmaf(xs[lr][k], w3[k * D_ + c], accv);
    out[(size_t)(r0 + lr) * D_ + c] = accv;
}

// ---------------- launch ----------------
extern "C" void kernel_launch(void* const* d_in, const int* in_sizes, int n_in,
                              void* d_out, int out_size)
{
    (void)in_sizes; (void)n_in; (void)out_size;
    const float* states = (const float*)d_in[0];
    const int*   action = (const int*)  d_in[1];
    const float* ew1 = (const float*)d_in[2];
    const float* eb1 = (const float*)d_in[3];
    const float* ew2 = (const float*)d_in[4];
    const float* eb2 = (const float*)d_in[5];
    const float* eg  = (const float*)d_in[6];
    const float* ebt = (const float*)d_in[7];
    const float* ew3 = (const float*)d_in[8];
    const float* eb3 = (const float*)d_in[9];
    const float* nw1 = (const float*)d_in[10];
    const float* nb1 = (const float*)d_in[11];
    const float* nw2 = (const float*)d_in[12];
    const float* nb2 = (const float*)d_in[13];
    const float* ng  = (const float*)d_in[14];
    const float* nbt = (const float*)d_in[15];
    const float* nw3 = (const float*)d_in[16];
    const float* nb3 = (const float*)d_in[17];
    float* out = (float*)d_out;

    static bool attrSet = false;
    if (!attrSet) {
        cudaFuncSetAttribute(tg<0>, cudaFuncAttributeMaxDynamicSharedMemorySize, SMEM_SZ);
        cudaFuncSetAttribute(tg<1>, cudaFuncAttributeMaxDynamicSharedMemorySize, SMEM_SZ);
        cudaFuncSetAttribute(tg<2>, cudaFuncAttributeMaxDynamicSharedMemorySize, SMEM_SZ);
        cudaFuncSetAttribute(tg<3>, cudaFuncAttributeMaxDynamicSharedMemorySize, SMEM_SZ);
        cudaFuncSetAttribute(tg<4>, cudaFuncAttributeMaxDynamicSharedMemorySize, SMEM_SZ);
        cudaFuncSetAttribute(tg<5>, cudaFuncAttributeMaxDynamicSharedMemorySize, SMEM_SZ);
        attrSet = true;
    }

    bf16 *w0h, *w0l, *w1h, *w1l, *w2h, *w2l, *w3h, *w3l, *w4h, *w4l, *w5h, *w5l;
    bf16 *sth, *stl, *eh, *el, *sh, *sl, *a4h, *a4l, *n1h, *n1l;
    cudaGetSymbolAddress((void**)&w0h, gW0h); cudaGetSymbolAddress((void**)&w0l, gW0l);
    cudaGetSymbolAddress((void**)&w1h, gW1h); cudaGetSymbolAddress((void**)&w1l, gW1l);
    cudaGetSymbolAddress((void**)&w2h, gW2h); cudaGetSymbolAddress((void**)&w2l, gW2l);
    cudaGetSymbolAddress((void**)&w3h, gW3h); cudaGetSymbolAddress((void**)&w3l, gW3l);
    cudaGetSymbolAddress((void**)&w4h, gW4h); cudaGetSymbolAddress((void**)&w4l, gW4l);
    cudaGetSymbolAddress((void**)&w5h, gW5h); cudaGetSymbolAddress((void**)&w5l, gW5l);
    cudaGetSymbolAddress((void**)&sth, gSTh); cudaGetSymbolAddress((void**)&stl, gSTl);
    cudaGetSymbolAddress((void**)&eh,  gEh);  cudaGetSymbolAddress((void**)&el,  gEl);
    cudaGetSymbolAddress((void**)&sh,  gSh);  cudaGetSymbolAddress((void**)&sl,  gSl);
    cudaGetSymbolAddress((void**)&a4h, gA4h); cudaGetSymbolAddress((void**)&a4l, gA4l);
    cudaGetSymbolAddress((void**)&n1h, gN1h); cudaGetSymbolAddress((void**)&n1l, gN1l);

    prep_all<<<(1097728 + 255) / 256, 256>>>(ew1, ew2, ew3, nw1, nw2);
    prep_states<<<(NN * D_ + 255) / 256, 256>>>(states);

    dim3 blk(256);
    tg<0><<<dim3(4, NN / 128), blk, SMEM_SZ>>>(sth, stl, w0h, w0l, eb1, nullptr, nullptr, 0);
    tg<1><<<dim3(4, NN / 128), blk, SMEM_SZ>>>(sth, stl, w1h, w1l, nullptr, nullptr, nullptr, 0);

    for (int s = 0; s < NSLICE; s++) {
        esplit<<<ESL * 64 / 256, 256>>>(s * ESL);
        tg<2><<<dim3(4, ESL / 128), blk, SMEM_SZ>>>(eh, el, w2h, w2l, eb2, nullptr, nullptr, s * ESL);
        ln_sum_k<<<NSL / 8, 256>>>(eg, ebt, s * NSL);
    }

    tg<3><<<dim3(4, NN / 128), blk, SMEM_SZ>>>(sh,  sl,  w3h, w3l, eb3, nullptr, nullptr, 0);
    tg<4><<<dim3(4, NN / 128), blk, SMEM_SZ>>>(a4h, a4l, w4h, w4l, nb1, action, nw1, 0);
    tg<5><<<dim3(4, NN / 128), blk, SMEM_SZ>>>(n1h, n1l, w5h, w5l, nb2, nullptr, nullptr, 0);
    ln2_k<<<NN / 8, 256>>>(ng, nbt);
    n3_k<<<NN / 8, 256>>>(nw3, nb3, out);
}

// round 8
// speedup vs baseline: 1.3528x; 1.3528x over previous
#include <cuda_runtime.h>
#include <cuda_fp16.h>
#include <cstdint>

#define CONST __restrict__
using f16 = __half;

static constexpr int B_  = 1024;
static constexpr int KO  = 10;
static constexpr int D_  = 32;
static constexpr int H_  = 512;
static constexpr int NN  = B_ * KO;     // 10240
static constexpr int EPN = KO - 1;      // 9
static constexpr int NE  = NN * EPN;    // 92160
static constexpr float EPS = 1e-5f;
static constexpr int K4  = 544;

static constexpr int NSLICE = 4;
static constexpr int ESL = NE / NSLICE;
static constexpr int NSL = NN / NSLICE;

// ---------------- scratch ----------------
__device__ __align__(16) f16 gST[NN * D_];                 // states fp16
__device__ float gP[NN * H_], gQ[NN * H_];                 // fp32 (pre-relu halves)
__device__ __align__(16) f16 gE[(size_t)NE * H_];          // edge A plane (94 MB)
__device__ float gH2[(size_t)NE * H_];                     // edge MLP hidden2 (fp32)
__device__ __align__(16) f16 gS [NN * H_];                 // summed LN-relu
__device__ __align__(16) f16 gA4[NN * K4];                 // node input [x | agg]
__device__ __align__(16) f16 gN1[NN * H_];
__device__ float gN2r[NN * H_], gN2[NN * H_];

// fp16-split transposed weights [N][K] (hi/lo)
__device__ __align__(16) f16 gW0h[2 * H_ * 32], gW0l[2 * H_ * 32];  // ew1 (P|Q merged)
__device__ __align__(16) f16 gW2h[H_ * H_],  gW2l[H_ * H_];
__device__ __align__(16) f16 gW3h[H_ * H_],  gW3l[H_ * H_];
__device__ __align__(16) f16 gW4h[H_ * K4],  gW4l[H_ * K4];
__device__ __align__(16) f16 gW5h[H_ * H_],  gW5l[H_ * H_];

// ---------------- helpers ----------------
__device__ __forceinline__ uint32_t s2u(const void* p) {
    uint32_t a;
    asm("{ .reg .u64 t; cvta.to.shared.u64 t, %1; cvt.u32.u64 %0, t; }" : "=r"(a) : "l"(p));
    return a;
}
__device__ __forceinline__ void cp16(uint32_t s, const void* g) {
    asm volatile("cp.async.cg.shared.global [%0], [%1], 16;" :: "r"(s), "l"(g));
}
__device__ __forceinline__ void ldsm4(uint32_t* r, uint32_t a) {
    asm volatile("ldmatrix.sync.aligned.m8n8.x4.shared.b16 {%0,%1,%2,%3}, [%4];"
        : "=r"(r[0]), "=r"(r[1]), "=r"(r[2]), "=r"(r[3]) : "r"(a));
}
__device__ __forceinline__ void ldsm2(uint32_t& r0, uint32_t& r1, uint32_t a) {
    asm volatile("ldmatrix.sync.aligned.m8n8.x2.shared.b16 {%0,%1}, [%2];"
        : "=r"(r0), "=r"(r1) : "r"(a));
}
__device__ __forceinline__ void mma_f16(float* c, const uint32_t* a, uint32_t b0, uint32_t b1) {
    asm("mma.sync.aligned.m16n8k16.row.col.f32.f16.f16.f32 "
        "{%0,%1,%2,%3}, {%4,%5,%6,%7}, {%8,%9}, {%0,%1,%2,%3};\n"
        : "+f"(c[0]), "+f"(c[1]), "+f"(c[2]), "+f"(c[3])
        : "r"(a[0]), "r"(a[1]), "r"(a[2]), "r"(a[3]), "r"(b0), "r"(b1));
}
__device__ __forceinline__ uint32_t pkh(float a, float b) {
    __half2 t; t.x = __float2half_rn(a); t.y = __float2half_rn(b);
    return *(uint32_t*)&t;
}

// ---------------- weight prep: fp16 hi/lo split + transpose ----------------
__global__ void prep_all(const float* CONST ew1, const float* CONST ew2,
                         const float* CONST ew3, const float* CONST nw1,
                         const float* CONST nw2)
{
    int idx = blockIdx.x * 256 + threadIdx.x;
    if (idx >= 1097728) return;
    const float* src; f16 *dh, *dl; int K, off, skip = 0, merged = 0;
    if      (idx < 32768)  { src = ew1; dh = gW0h; dl = gW0l; K = 32;  off = 0; merged = 1; }
    else if (idx < 294912) { src = ew2; dh = gW2h; dl = gW2l; K = 512; off = 32768; }
    else if (idx < 557056) { src = ew3; dh = gW3h; dl = gW3l; K = 512; off = 294912; }
    else if (idx < 835584) { src = nw1; dh = gW4h; dl = gW4l; K = K4;  off = 557056; skip = 1; }
    else                   { src = nw2; dh = gW5h; dl = gW5l; K = 512; off = 835584; }
    int i2 = idx - off;
    int k = i2 % K, n = i2 / K;
    float v;
    if (merged) {
        // n in [0,1024): first 512 cols = P weights (ew1 rows 0-31), next 512 = Q (rows 32-63)
        int sr = (n < 512) ? k : 32 + k;
        int sn = (n < 512) ? n : n - 512;
        v = src[(size_t)sr * H_ + sn];
    } else {
        int sr = (skip && k >= 32) ? k + 4 : k;
        v = src[(size_t)sr * H_ + n];
    }
    f16 h = __float2half_rn(v);
    dh[i2] = h;
    dl[i2] = __float2half_rn(v - __half2float(h));
}

__global__ void prep_states(const float* CONST s)
{
    int idx = blockIdx.x * 256 + threadIdx.x;
    if (idx >= NN * D_) return;
    f16 h = __float2half_rn(s[idx]);
    gST[idx] = h;
    int r = idx >> 5, c = idx & 31;
    gA4[r * K4 + c] = h;
}

// ---------------- edge A: relu(P+Q) -> fp16 plane ----------------
__global__ __launch_bounds__(256) void esplit(int edgeOff)
{
    int gi = blockIdx.x * 256 + threadIdx.x;
    int e = edgeOff + (gi >> 6);
    int cg = (gi & 63) * 8;
    int node = e / EPN;
    int jj = e - node * EPN;
    int i = node % KO;
    int j = jj + (jj >= i ? 1 : 0);
    int cn = node - i + j;

    float4 p0 = *(const float4*)(gP + (size_t)node * H_ + cg);
    float4 p1 = *(const float4*)(gP + (size_t)node * H_ + cg + 4);
    float4 q0 = *(const float4*)(gQ + (size_t)cn * H_ + cg);
    float4 q1 = *(const float4*)(gQ + (size_t)cn * H_ + cg + 4);
    f16 o[8];
    o[0] = __float2half_rn(fmaxf(p0.x + q0.x, 0.f));
    o[1] = __float2half_rn(fmaxf(p0.y + q0.y, 0.f));
    o[2] = __float2half_rn(fmaxf(p0.z + q0.z, 0.f));
    o[3] = __float2half_rn(fmaxf(p0.w + q0.w, 0.f));
    o[4] = __float2half_rn(fmaxf(p1.x + q1.x, 0.f));
    o[5] = __float2half_rn(fmaxf(p1.y + q1.y, 0.f));
    o[6] = __float2half_rn(fmaxf(p1.z + q1.z, 0.f));
    o[7] = __float2half_rn(fmaxf(p1.w + q1.w, 0.f));
    *(uint4*)(gE + (size_t)e * H_ + cg) = *(const uint4*)o;
}

// ---------------- 2-term fp16 mma GEMM: C = A @ (Wh + Wl) ----------------
// MODE 0: gP/gQ fp32 = ST@[ew1a|ew1b] (+eb1 on P half)  (K=32, N=1024)
// MODE 2: gH2 fp32   = E@ew2 + eb2                      (K=512, M=NE, sliced)
// MODE 3: gA4[:,32:] = fp16(S@ew3 + 9*eb3)              (K=512)
// MODE 4: gN1 fp16   = relu(A4@nw1' + nb1 + row)        (K=544)
// MODE 5: gN2r fp32  = N1@nw2 + nb2                     (K=512)
static constexpr int LDP = 40;
static constexpr int SZA = 128 * LDP * 2;   // 10240 B
static constexpr int STG = 3 * SZA;         // 30720 B per stage (A, Wh, Wl)
static constexpr int SMEM_SZ = 2 * STG;     // 61440 B

template <int MODE>
__global__ __launch_bounds__(256, 2)
void tg(const f16* CONST A_, const f16* CONST Wh_, const f16* CONST Wl_,
        const float* CONST bias, const int* CONST act,
        const float* CONST nw1full, int rowOff)
{
    constexpr int KT = (MODE == 0) ? 32 : (MODE == 4 ? K4 : 512);
    constexpr int NC = KT / 32;
    extern __shared__ char smraw[];
    const uint32_t sbase = s2u(smraw);

    const int tid = threadIdx.x, warp = tid >> 5, lane = tid & 31;
    const int rowBase = rowOff + blockIdx.y * 128;
    const int colBase = blockIdx.x * 128;
    const int fr = tid >> 1, fks = (tid & 1) * 16;

    const f16* pA  = A_  + (size_t)(rowBase + fr) * KT + fks;
    const f16* pWh = Wh_ + (size_t)(colBase + fr) * KT + fks;
    const f16* pWl = Wl_ + (size_t)(colBase + fr) * KT + fks;

    const uint32_t wb = sbase + (fr * LDP + fks) * 2;
    auto ldgsts = [&](int stg, int k0) {
        const uint32_t d = wb + stg * STG;
        cp16(d,               pA + k0);   cp16(d + 16,           pA + k0 + 8);
        cp16(d + SZA,         pWh + k0);  cp16(d + SZA + 16,     pWh + k0 + 8);
        cp16(d + 2 * SZA,     pWl + k0);  cp16(d + 2 * SZA + 16, pWl + k0 + 8);
        asm volatile("cp.async.commit_group;");
    };

    const int wm = warp >> 2, wn = warp & 3;     // 2x4 warps, tile 64x32
    const int la_row = lane & 15, la_sel = lane >> 4;
    const int lb_row = lane & 7,  lb_sel = (lane >> 3) & 1;

    float acc[4][4][4];
    #pragma unroll
    for (int a = 0; a < 4; a++)
        #pragma unroll
        for (int b = 0; b < 4; b++)
            #pragma unroll
            for (int c = 0; c < 4; c++) acc[a][b][c] = 0.f;

    ldgsts(0, 0);
    for (int c = 0; c < NC; c++) {
        if (c + 1 < NC) {
            ldgsts((c + 1) & 1, (c + 1) * 32);
            asm volatile("cp.async.wait_group 1;");
        } else {
            asm volatile("cp.async.wait_group 0;");
        }
        __syncthreads();

        const uint32_t uA  = sbase + (c & 1) * STG;
        const uint32_t uWh = uA + SZA;
        const uint32_t uWl = uA + 2 * SZA;
        #pragma unroll
        for (int kf = 0; kf < 2; kf++) {
            const int kb = kf * 16;
            uint32_t ah[4][4];
            #pragma unroll
            for (int mt = 0; mt < 4; mt++) {
                const uint32_t ra =
                    (uint32_t)(((wm * 64 + mt * 16 + la_row) * LDP + kb + la_sel * 8) * 2);
                ldsm4(ah[mt], uA + ra);
            }
            #pragma unroll
            for (int nt = 0; nt < 4; nt++) {
                const uint32_t rb =
                    (uint32_t)(((wn * 32 + nt * 8 + lb_row) * LDP + kb + lb_sel * 8) * 2);
                uint32_t wh0, wh1, wl0, wl1;
                ldsm2(wh0, wh1, uWh + rb);
                ldsm2(wl0, wl1, uWl + rb);
                #pragma unroll
                for (int mt = 0; mt < 4; mt++)
                    mma_f16(acc[mt][nt], ah[mt], wh0, wh1);
                #pragma unroll
                for (int mt = 0; mt < 4; mt++)
                    mma_f16(acc[mt][nt], ah[mt], wl0, wl1);
            }
        }
        __syncthreads();
    }

    // ---- epilogue ----
    const int g = lane >> 2, tg2 = (lane & 3) * 2;
    #pragma unroll
    for (int mt = 0; mt < 4; mt++) {
        const int row0 = rowBase + wm * 64 + mt * 16 + g;
        const int row1 = row0 + 8;
        int a0r = 0, a1r = 0;
        if constexpr (MODE == 4) { a0r = act[row0 / KO]; a1r = act[row1 / KO]; }
        #pragma unroll
        for (int nt = 0; nt < 4; nt++) {
            const int col = colBase + wn * 32 + nt * 8 + tg2;
            float v0 = acc[mt][nt][0], v1 = acc[mt][nt][1];
            float v2 = acc[mt][nt][2], v3 = acc[mt][nt][3];
            if constexpr (MODE == 0) {
                if (colBase < 512) {   // P half: + eb1
                    float b0 = bias[col], b1 = bias[col + 1];
                    *(float2*)(gP + (size_t)row0 * H_ + col) = make_float2(v0 + b0, v1 + b1);
                    *(float2*)(gP + (size_t)row1 * H_ + col) = make_float2(v2 + b0, v3 + b1);
                } else {               // Q half
                    int cq = col - 512;
                    *(float2*)(gQ + (size_t)row0 * H_ + cq) = make_float2(v0, v1);
                    *(float2*)(gQ + (size_t)row1 * H_ + cq) = make_float2(v2, v3);
                }
            }
            if constexpr (MODE == 2) {
                float b0 = bias[col], b1 = bias[col + 1];
                *(float2*)(gH2 + (size_t)row0 * H_ + col) = make_float2(v0 + b0, v1 + b1);
                *(float2*)(gH2 + (size_t)row1 * H_ + col) = make_float2(v2 + b0, v3 + b1);
            }
            if constexpr (MODE == 3) {
                float b0 = 9.f * bias[col], b1 = 9.f * bias[col + 1];
                *(uint32_t*)(gA4 + (size_t)row0 * K4 + 32 + col) = pkh(v0 + b0, v1 + b1);
                *(uint32_t*)(gA4 + (size_t)row1 * K4 + 32 + col) = pkh(v2 + b0, v3 + b1);
            }
            if constexpr (MODE == 4) {
                float b0 = bias[col], b1 = bias[col + 1];
                const float* r0p = nw1full + (size_t)(32 + a0r) * H_;
                const float* r1p = nw1full + (size_t)(32 + a1r) * H_;
                *(uint32_t*)(gN1 + (size_t)row0 * H_ + col) =
                    pkh(fmaxf(v0 + b0 + r0p[col], 0.f), fmaxf(v1 + b1 + r0p[col + 1], 0.f));
                *(uint32_t*)(gN1 + (size_t)row1 * H_ + col) =
                    pkh(fmaxf(v2 + b0 + r1p[col], 0.f), fmaxf(v3 + b1 + r1p[col + 1], 0.f));
            }
            if constexpr (MODE == 5) {
                float b0 = bias[col], b1 = bias[col + 1];
                *(float2*)(gN2r + (size_t)row0 * H_ + col) = make_float2(v0 + b0, v1 + b1);
                *(float2*)(gN2r + (size_t)row1 * H_ + col) = make_float2(v2 + b0, v3 + b1);
            }
        }
    }
}

// ---------------- LN + relu + 9-row sum -> fp16 S plane ----------------
__global__ __launch_bounds__(256)
void ln_sum_k(const float* CONST g, const float* CONST bt, int nodeOff)
{
    const int tid = threadIdx.x, warp = tid >> 5, lane = tid & 31;
    const int n = nodeOff + blockIdx.x * 8 + warp;
    const float4* gg = (const float4*)g;
    const float4* bb = (const float4*)bt;
    float4 G[4], Bt[4], acc[4];
    #pragma unroll
    for (int j = 0; j < 4; j++) {
        G[j] = gg[lane + 32 * j];
        Bt[j] = bb[lane + 32 * j];
        acc[j] = make_float4(0.f, 0.f, 0.f, 0.f);
    }
    for (int e = 0; e < EPN; e++) {
        const float4* rp = (const float4*)(gH2 + (size_t)(n * EPN + e) * H_);
        float4 v[4];
        float s = 0.f, sq = 0.f;
        #pragma unroll
        for (int j = 0; j < 4; j++) {
            v[j] = rp[lane + 32 * j];
            s  += v[j].x + v[j].y + v[j].z + v[j].w;
            sq += v[j].x * v[j].x + v[j].y * v[j].y + v[j].z * v[j].z + v[j].w * v[j].w;
        }
        #pragma unroll
        for (int o = 16; o > 0; o >>= 1) {
            s  += __shfl_xor_sync(0xffffffff, s, o);
            sq += __shfl_xor_sync(0xffffffff, sq, o);
        }
        const float mean = s * (1.f / 512.f);
        const float rstd = rsqrtf(sq * (1.f / 512.f) - mean * mean + EPS);
        #pragma unroll
        for (int j = 0; j < 4; j++) {
            acc[j].x += fmaxf((v[j].x - mean) * rstd * G[j].x + Bt[j].x, 0.f);
            acc[j].y += fmaxf((v[j].y - mean) * rstd * G[j].y + Bt[j].y, 0.f);
            acc[j].z += fmaxf((v[j].z - mean) * rstd * G[j].z + Bt[j].z, 0.f);
            acc[j].w += fmaxf((v[j].w - mean) * rstd * G[j].w + Bt[j].w, 0.f);
        }
    }
    #pragma unroll
    for (int j = 0; j < 4; j++) {
        const int cb = (lane + 32 * j) * 4;
        *(uint2*)(gS + (size_t)n * H_ + cb) =
            make_uint2(pkh(acc[j].x, acc[j].y), pkh(acc[j].z, acc[j].w));
    }
}

// ---------------- LN + relu of gN2r ----------------
__global__ __launch_bounds__(256)
void ln2_k(const float* CONST g, const float* CONST bt)
{
    const int tid = threadIdx.x, warp = tid >> 5, lane = tid & 31;
    const int n = blockIdx.x * 8 + warp;
    const float4* rp = (const float4*)(gN2r + (size_t)n * H_);
    float4 v[4];
    float s = 0.f, sq = 0.f;
    #pragma unroll
    for (int j = 0; j < 4; j++) {
        v[j] = rp[lane + 32 * j];
        s  += v[j].x + v[j].y + v[j].z + v[j].w;
        sq += v[j].x * v[j].x + v[j].y * v[j].y + v[j].z * v[j].z + v[j].w * v[j].w;
    }
    #pragma unroll
    for (int o = 16; o > 0; o >>= 1) {
        s  += __shfl_xor_sync(0xffffffff, s, o);
        sq += __shfl_xor_sync(0xffffffff, sq, o);
    }
    const float mean = s * (1.f / 512.f);
    const float rstd = rsqrtf(sq * (1.f / 512.f) - mean * mean + EPS);
    float4* op = (float4*)(gN2 + (size_t)n * H_);
    #pragma unroll
    for (int j = 0; j < 4; j++) {
        const int c = (lane + 32 * j) * 4;
        float4 o4;
        o4.x = fmaxf((v[j].x - mean) * rstd * g[c]     + bt[c],     0.f);
        o4.y = fmaxf((v[j].y - mean) * rstd * g[c + 1] + bt[c + 1], 0.f);
        o4.z = fmaxf((v[j].z - mean) * rstd * g[c + 2] + bt[c + 2], 0.f);
        o4.w = fmaxf((v[j].w - mean) * rstd * g[c + 3] + bt[c + 3], 0.f);
        op[lane + 32 * j] = o4;
    }
}

// ---------------- out = gN2 @ nw3 + nb3 ----------------
__global__ __launch_bounds__(256)
void n3_k(const float* CONST w3, const float* CONST b3, float* CONST out)
{
    __shared__ float xs[8][H_];
    const int r0 = blockIdx.x * 8;
    const int t = threadIdx.x;
    for (int i = t; i < 8 * H_; i += 256)
        xs[i >> 9][i & 511] = gN2[(size_t)(r0 + (i >> 9)) * H_ + (i & 511)];
    __syncthreads();
    const int lr = t >> 5, c = t & 31;
    float accv = b3[c];
    #pragma unroll 8
    for (int k = 0; k < H_; k++)
        accv = fmaf(xs[lr][k], w3[k * D_ + c], accv);
    out[(size_t)(r0 + lr) * D_ + c] = accv;
}

// ---------------- launch ----------------
extern "C" void kernel_launch(void* const* d_in, const int* in_sizes, int n_in,
                              void* d_out, int out_size)
{
    (void)in_sizes; (void)n_in; (void)out_size;
    const float* states = (const float*)d_in[0];
    const int*   action = (const int*)  d_in[1];
    const float* ew1 = (const float*)d_in[2];
    const float* eb1 = (const float*)d_in[3];
    const float* ew2 = (const float*)d_in[4];
    const float* eb2 = (const float*)d_in[5];
    const float* eg  = (const float*)d_in[6];
    const float* ebt = (const float*)d_in[7];
    const float* ew3 = (const float*)d_in[8];
    const float* eb3 = (const float*)d_in[9];
    const float* nw1 = (const float*)d_in[10];
    const float* nb1 = (const float*)d_in[11];
    const float* nw2 = (const float*)d_in[12];
    const float* nb2 = (const float*)d_in[13];
    const float* ng  = (const float*)d_in[14];
    const float* nbt = (const float*)d_in[15];
    const float* nw3 = (const float*)d_in[16];
    const float* nb3 = (const float*)d_in[17];
    float* out = (float*)d_out;

    static bool attrSet = false;
    if (!attrSet) {
        cudaFuncSetAttribute(tg<0>, cudaFuncAttributeMaxDynamicSharedMemorySize, SMEM_SZ);
        cudaFuncSetAttribute(tg<2>, cudaFuncAttributeMaxDynamicSharedMemorySize, SMEM_SZ);
        cudaFuncSetAttribute(tg<3>, cudaFuncAttributeMaxDynamicSharedMemorySize, SMEM_SZ);
        cudaFuncSetAttribute(tg<4>, cudaFuncAttributeMaxDynamicSharedMemorySize, SMEM_SZ);
        cudaFuncSetAttribute(tg<5>, cudaFuncAttributeMaxDynamicSharedMemorySize, SMEM_SZ);
        attrSet = true;
    }

    f16 *w0h, *w0l, *w2h, *w2l, *w3h, *w3l, *w4h, *w4l, *w5h, *w5l;
    f16 *st, *e, *sS, *a4, *n1;
    cudaGetSymbolAddress((void**)&w0h, gW0h); cudaGetSymbolAddress((void**)&w0l, gW0l);
    cudaGetSymbolAddress((void**)&w2h, gW2h); cudaGetSymbolAddress((void**)&w2l, gW2l);
    cudaGetSymbolAddress((void**)&w3h, gW3h); cudaGetSymbolAddress((void**)&w3l, gW3l);
    cudaGetSymbolAddress((void**)&w4h, gW4h); cudaGetSymbolAddress((void**)&w4l, gW4l);
    cudaGetSymbolAddress((void**)&w5h, gW5h); cudaGetSymbolAddress((void**)&w5l, gW5l);
    cudaGetSymbolAddress((void**)&st, gST);
    cudaGetSymbolAddress((void**)&e,  gE);
    cudaGetSymbolAddress((void**)&sS, gS);
    cudaGetSymbolAddress((void**)&a4, gA4);
    cudaGetSymbolAddress((void**)&n1, gN1);

    prep_all<<<(1097728 + 255) / 256, 256>>>(ew1, ew2, ew3, nw1, nw2);
    prep_states<<<(NN * D_ + 255) / 256, 256>>>(states);

    dim3 blk(256);
    // P and Q in one launch: N = 1024 (first 512 cols -> P (+eb1), rest -> Q)
    tg<0><<<dim3(8, NN / 128), blk, SMEM_SZ>>>(st, w0h, w0l, eb1, nullptr, nullptr, 0);

    for (int s = 0; s < NSLICE; s++) {
        esplit<<<ESL * 64 / 256, 256>>>(s * ESL);
        tg<2><<<dim3(4, ESL / 128), blk, SMEM_SZ>>>(e, w2h, w2l, eb2, nullptr, nullptr, s * ESL);
        ln_sum_k<<<NSL / 8, 256>>>(eg, ebt, s * NSL);
    }

    tg<3><<<dim3(4, NN / 128), blk, SMEM_SZ>>>(sS, w3h, w3l, eb3, nullptr, nullptr, 0);
    tg<4><<<dim3(4, NN / 128), blk, SMEM_SZ>>>(a4, w4h, w4l, nb1, action, nw1, 0);
    tg<5><<<dim3(4, NN / 128), blk, SMEM_SZ>>>(n1, w5h, w5l, nb2, nullptr, nullptr, 0);
    ln2_k<<<NN / 8, 256>>>(ng, nbt);
    n3_k<<<NN / 8, 256>>>(nw3, nb3, out);
}

// round 9
// speedup vs baseline: 1.6488x; 1.2188x over previous
#include <cuda_runtime.h>
#include <cuda_fp16.h>
#include <cstdint>

#define CONST __restrict__
using f16 = __half;

static constexpr int B_  = 1024;
static constexpr int KO  = 10;
static constexpr int D_  = 32;
static constexpr int H_  = 512;
static constexpr int NN  = B_ * KO;     // 10240
static constexpr int EPN = KO - 1;      // 9
static constexpr int NE  = NN * EPN;    // 92160
static constexpr float EPS = 1e-5f;
static constexpr int K4  = 544;

static constexpr int NSLICE = 4;
static constexpr int ESL = NE / NSLICE;
static constexpr int NSL = NN / NSLICE;

// ---------------- scratch ----------------
__device__ __align__(16) f16 gST[NN * D_];
__device__ float gP[NN * H_], gQ[NN * H_];
__device__ __align__(16) f16 gE[(size_t)NE * H_];
__device__ float gH2[(size_t)NE * H_];
__device__ __align__(16) f16 gS [NN * H_];
__device__ __align__(16) f16 gA4[NN * K4];
__device__ __align__(16) f16 gN1[NN * H_];
__device__ float gN2r[NN * H_], gN2[NN * H_];

// fp16-split transposed weights [N][K] (hi/lo)
__device__ __align__(16) f16 gW0h[2 * H_ * 32], gW0l[2 * H_ * 32];
__device__ __align__(16) f16 gW2h[H_ * H_],  gW2l[H_ * H_];
__device__ __align__(16) f16 gW3h[H_ * H_],  gW3l[H_ * H_];
__device__ __align__(16) f16 gW4h[H_ * K4],  gW4l[H_ * K4];
__device__ __align__(16) f16 gW5h[H_ * H_],  gW5l[H_ * H_];

// ---------------- helpers ----------------
__device__ __forceinline__ uint32_t s2u(const void* p) {
    uint32_t a;
    asm("{ .reg .u64 t; cvta.to.shared.u64 t, %1; cvt.u32.u64 %0, t; }" : "=r"(a) : "l"(p));
    return a;
}
__device__ __forceinline__ void cp16(uint32_t s, const void* g) {
    asm volatile("cp.async.cg.shared.global [%0], [%1], 16;" :: "r"(s), "l"(g));
}
__device__ __forceinline__ void ldsm4(uint32_t* r, uint32_t a) {
    asm volatile("ldmatrix.sync.aligned.m8n8.x4.shared.b16 {%0,%1,%2,%3}, [%4];"
        : "=r"(r[0]), "=r"(r[1]), "=r"(r[2]), "=r"(r[3]) : "r"(a));
}
__device__ __forceinline__ void ldsm2(uint32_t& r0, uint32_t& r1, uint32_t a) {
    asm volatile("ldmatrix.sync.aligned.m8n8.x2.shared.b16 {%0,%1}, [%2];"
        : "=r"(r0), "=r"(r1) : "r"(a));
}
__device__ __forceinline__ void mma_f16(float* c, const uint32_t* a, uint32_t b0, uint32_t b1) {
    asm("mma.sync.aligned.m16n8k16.row.col.f32.f16.f16.f32 "
        "{%0,%1,%2,%3}, {%4,%5,%6,%7}, {%8,%9}, {%0,%1,%2,%3};\n"
        : "+f"(c[0]), "+f"(c[1]), "+f"(c[2]), "+f"(c[3])
        : "r"(a[0]), "r"(a[1]), "r"(a[2]), "r"(a[3]), "r"(b0), "r"(b1));
}
__device__ __forceinline__ uint32_t pkh(float a, float b) {
    __half2 t; t.x = __float2half_rn(a); t.y = __float2half_rn(b);
    return *(uint32_t*)&t;
}

// ---------------- weight prep ----------------
__global__ void prep_all(const float* CONST ew1, const float* CONST ew2,
                         const float* CONST ew3, const float* CONST nw1,
                         const float* CONST nw2)
{
    int idx = blockIdx.x * 256 + threadIdx.x;
    if (idx >= 1097728) return;
    const float* src; f16 *dh, *dl; int K, off, skip = 0, merged = 0;
    if      (idx < 32768)  { src = ew1; dh = gW0h; dl = gW0l; K = 32;  off = 0; merged = 1; }
    else if (idx < 294912) { src = ew2; dh = gW2h; dl = gW2l; K = 512; off = 32768; }
    else if (idx < 557056) { src = ew3; dh = gW3h; dl = gW3l; K = 512; off = 294912; }
    else if (idx < 835584) { src = nw1; dh = gW4h; dl = gW4l; K = K4;  off = 557056; skip = 1; }
    else                   { src = nw2; dh = gW5h; dl = gW5l; K = 512; off = 835584; }
    int i2 = idx - off;
    int k = i2 % K, n = i2 / K;
    float v;
    if (merged) {
        int sr = (n < 512) ? k : 32 + k;
        int sn = (n < 512) ? n : n - 512;
        v = src[(size_t)sr * H_ + sn];
    } else {
        int sr = (skip && k >= 32) ? k + 4 : k;
        v = src[(size_t)sr * H_ + n];
    }
    f16 h = __float2half_rn(v);
    dh[i2] = h;
    dl[i2] = __float2half_rn(v - __half2float(h));
}

__global__ void prep_states(const float* CONST s)
{
    int idx = blockIdx.x * 256 + threadIdx.x;
    if (idx >= NN * D_) return;
    f16 h = __float2half_rn(s[idx]);
    gST[idx] = h;
    int r = idx >> 5, c = idx & 31;
    gA4[r * K4 + c] = h;
}

// ---------------- edge A: relu(P+Q) -> fp16 plane ----------------
__global__ __launch_bounds__(256) void esplit(int edgeOff)
{
    int gi = blockIdx.x * 256 + threadIdx.x;
    int e = edgeOff + (gi >> 6);
    int cg = (gi & 63) * 8;
    int node = e / EPN;
    int jj = e - node * EPN;
    int i = node % KO;
    int j = jj + (jj >= i ? 1 : 0);
    int cn = node - i + j;

    float4 p0 = *(const float4*)(gP + (size_t)node * H_ + cg);
    float4 p1 = *(const float4*)(gP + (size_t)node * H_ + cg + 4);
    float4 q0 = *(const float4*)(gQ + (size_t)cn * H_ + cg);
    float4 q1 = *(const float4*)(gQ + (size_t)cn * H_ + cg + 4);
    f16 o[8];
    o[0] = __float2half_rn(fmaxf(p0.x + q0.x, 0.f));
    o[1] = __float2half_rn(fmaxf(p0.y + q0.y, 0.f));
    o[2] = __float2half_rn(fmaxf(p0.z + q0.z, 0.f));
    o[3] = __float2half_rn(fmaxf(p0.w + q0.w, 0.f));
    o[4] = __float2half_rn(fmaxf(p1.x + q1.x, 0.f));
    o[5] = __float2half_rn(fmaxf(p1.y + q1.y, 0.f));
    o[6] = __float2half_rn(fmaxf(p1.z + q1.z, 0.f));
    o[7] = __float2half_rn(fmaxf(p1.w + q1.w, 0.f));
    *(uint4*)(gE + (size_t)e * H_ + cg) = *(const uint4*)o;
}

// ---------------- fp16 mma GEMM; mode 2 = 1-term, others = 2-term ----------------
static constexpr int LDP = 40;
static constexpr int SZA = 128 * LDP * 2;   // 10240 B
static constexpr int STG = 3 * SZA;         // 30720 B per stage
static constexpr int SMEM_SZ = 2 * STG;     // 61440 B

template <int MODE>
__global__ __launch_bounds__(256, 2)
void tg(const f16* CONST A_, const f16* CONST Wh_, const f16* CONST Wl_,
        const float* CONST bias, const int* CONST act,
        const float* CONST nw1full, int rowOff)
{
    constexpr int KT = (MODE == 0) ? 32 : (MODE == 4 ? K4 : 512);
    constexpr int NC = KT / 32;
    constexpr int TERMS = (MODE == 2) ? 1 : 2;   // big edge GEMM: single-term fp16
    extern __shared__ char smraw[];
    const uint32_t sbase = s2u(smraw);

    const int tid = threadIdx.x, warp = tid >> 5, lane = tid & 31;
    const int rowBase = rowOff + blockIdx.y * 128;
    const int colBase = blockIdx.x * 128;
    const int fr = tid >> 1, fks = (tid & 1) * 16;

    const f16* pA  = A_  + (size_t)(rowBase + fr) * KT + fks;
    const f16* pWh = Wh_ + (size_t)(colBase + fr) * KT + fks;
    const f16* pWl = Wl_ + (size_t)(colBase + fr) * KT + fks;

    const uint32_t wb = sbase + (fr * LDP + fks) * 2;
    auto ldgsts = [&](int stg, int k0) {
        const uint32_t d = wb + stg * STG;
        cp16(d,           pA + k0);   cp16(d + 16,       pA + k0 + 8);
        cp16(d + SZA,     pWh + k0);  cp16(d + SZA + 16, pWh + k0 + 8);
        if constexpr (TERMS == 2) {
            cp16(d + 2 * SZA, pWl + k0);
            cp16(d + 2 * SZA + 16, pWl + k0 + 8);
        }
        asm volatile("cp.async.commit_group;");
    };

    const int wm = warp >> 2, wn = warp & 3;     // 2x4 warps, tile 64x32
    const int la_row = lane & 15, la_sel = lane >> 4;
    const int lb_row = lane & 7,  lb_sel = (lane >> 3) & 1;

    float acc[4][4][4];
    #pragma unroll
    for (int a = 0; a < 4; a++)
        #pragma unroll
        for (int b = 0; b < 4; b++)
            #pragma unroll
            for (int c = 0; c < 4; c++) acc[a][b][c] = 0.f;

    ldgsts(0, 0);
    for (int c = 0; c < NC; c++) {
        if (c + 1 < NC) {
            ldgsts((c + 1) & 1, (c + 1) * 32);
            asm volatile("cp.async.wait_group 1;");
        } else {
            asm volatile("cp.async.wait_group 0;");
        }
        __syncthreads();

        const uint32_t uA  = sbase + (c & 1) * STG;
        const uint32_t uWh = uA + SZA;
        const uint32_t uWl = uA + 2 * SZA;
        #pragma unroll
        for (int kf = 0; kf < 2; kf++) {
            const int kb = kf * 16;
            uint32_t ah[4][4];
            #pragma unroll
            for (int mt = 0; mt < 4; mt++) {
                const uint32_t ra =
                    (uint32_t)(((wm * 64 + mt * 16 + la_row) * LDP + kb + la_sel * 8) * 2);
                ldsm4(ah[mt], uA + ra);
            }
            #pragma unroll
            for (int nt = 0; nt < 4; nt++) {
                const uint32_t rb =
                    (uint32_t)(((wn * 32 + nt * 8 + lb_row) * LDP + kb + lb_sel * 8) * 2);
                uint32_t wh0, wh1;
                ldsm2(wh0, wh1, uWh + rb);
                if constexpr (TERMS == 2) {
                    uint32_t wl0, wl1;
                    ldsm2(wl0, wl1, uWl + rb);
                    #pragma unroll
                    for (int mt = 0; mt < 4; mt++)
                        mma_f16(acc[mt][nt], ah[mt], wh0, wh1);
                    #pragma unroll
                    for (int mt = 0; mt < 4; mt++)
                        mma_f16(acc[mt][nt], ah[mt], wl0, wl1);
                } else {
                    #pragma unroll
                    for (int mt = 0; mt < 4; mt++)
                        mma_f16(acc[mt][nt], ah[mt], wh0, wh1);
                }
            }
        }
        __syncthreads();
    }

    // ---- epilogue ----
    const int g = lane >> 2, tg2 = (lane & 3) * 2;
    #pragma unroll
    for (int mt = 0; mt < 4; mt++) {
        const int row0 = rowBase + wm * 64 + mt * 16 + g;
        const int row1 = row0 + 8;
        int a0r = 0, a1r = 0;
        if constexpr (MODE == 4) { a0r = act[row0 / KO]; a1r = act[row1 / KO]; }
        #pragma unroll
        for (int nt = 0; nt < 4; nt++) {
            const int col = colBase + wn * 32 + nt * 8 + tg2;
            float v0 = acc[mt][nt][0], v1 = acc[mt][nt][1];
            float v2 = acc[mt][nt][2], v3 = acc[mt][nt][3];
            if constexpr (MODE == 0) {
                if (colBase < 512) {
                    float b0 = bias[col], b1 = bias[col + 1];
                    *(float2*)(gP + (size_t)row0 * H_ + col) = make_float2(v0 + b0, v1 + b1);
                    *(float2*)(gP + (size_t)row1 * H_ + col) = make_float2(v2 + b0, v3 + b1);
                } else {
                    int cq = col - 512;
                    *(float2*)(gQ + (size_t)row0 * H_ + cq) = make_float2(v0, v1);
                    *(float2*)(gQ + (size_t)row1 * H_ + cq) = make_float2(v2, v3);
                }
            }
            if constexpr (MODE == 2) {
                float b0 = bias[col], b1 = bias[col + 1];
                *(float2*)(gH2 + (size_t)row0 * H_ + col) = make_float2(v0 + b0, v1 + b1);
                *(float2*)(gH2 + (size_t)row1 * H_ + col) = make_float2(v2 + b0, v3 + b1);
            }
            if constexpr (MODE == 3) {
                float b0 = 9.f * bias[col], b1 = 9.f * bias[col + 1];
                *(uint32_t*)(gA4 + (size_t)row0 * K4 + 32 + col) = pkh(v0 + b0, v1 + b1);
                *(uint32_t*)(gA4 + (size_t)row1 * K4 + 32 + col) = pkh(v2 + b0, v3 + b1);
            }
            if constexpr (MODE == 4) {
                float b0 = bias[col], b1 = bias[col + 1];
                const float* r0p = nw1full + (size_t)(32 + a0r) * H_;
                const float* r1p = nw1full + (size_t)(32 + a1r) * H_;
                *(uint32_t*)(gN1 + (size_t)row0 * H_ + col) =
                    pkh(fmaxf(v0 + b0 + r0p[col], 0.f), fmaxf(v1 + b1 + r0p[col + 1], 0.f));
                *(uint32_t*)(gN1 + (size_t)row1 * H_ + col) =
                    pkh(fmaxf(v2 + b0 + r1p[col], 0.f), fmaxf(v3 + b1 + r1p[col + 1], 0.f));
            }
            if constexpr (MODE == 5) {
                float b0 = bias[col], b1 = bias[col + 1];
                *(float2*)(gN2r + (size_t)row0 * H_ + col) = make_float2(v0 + b0, v1 + b1);
                *(float2*)(gN2r + (size_t)row1 * H_ + col) = make_float2(v2 + b0, v3 + b1);
            }
        }
    }
}

// ---------------- LN + relu + 9-row sum -> fp16 S plane ----------------
__global__ __launch_bounds__(256)
void ln_sum_k(const float* CONST g, const float* CONST bt, int nodeOff)
{
    const int tid = threadIdx.x, warp = tid >> 5, lane = tid & 31;
    const int n = nodeOff + blockIdx.x * 8 + warp;
    const float4* gg = (const float4*)g;
    const float4* bb = (const float4*)bt;
    float4 G[4], Bt[4], acc[4];
    #pragma unroll
    for (int j = 0; j < 4; j++) {
        G[j] = gg[lane + 32 * j];
        Bt[j] = bb[lane + 32 * j];
        acc[j] = make_float4(0.f, 0.f, 0.f, 0.f);
    }
    for (int e = 0; e < EPN; e++) {
        const float4* rp = (const float4*)(gH2 + (size_t)(n * EPN + e) * H_);
        float4 v[4];
        float s = 0.f, sq = 0.f;
        #pragma unroll
        for (int j = 0; j < 4; j++) {
            v[j] = rp[lane + 32 * j];
            s  += v[j].x + v[j].y + v[j].z + v[j].w;
            sq += v[j].x * v[j].x + v[j].y * v[j].y + v[j].z * v[j].z + v[j].w * v[j].w;
        }
        #pragma unroll
        for (int o = 16; o > 0; o >>= 1) {
            s  += __shfl_xor_sync(0xffffffff, s, o);
            sq += __shfl_xor_sync(0xffffffff, sq, o);
        }
        const float mean = s * (1.f / 512.f);
        const float rstd = rsqrtf(sq * (1.f / 512.f) - mean * mean + EPS);
        #pragma unroll
        for (int j = 0; j < 4; j++) {
            acc[j].x += fmaxf((v[j].x - mean) * rstd * G[j].x + Bt[j].x, 0.f);
            acc[j].y += fmaxf((v[j].y - mean) * rstd * G[j].y + Bt[j].y, 0.f);
            acc[j].z += fmaxf((v[j].z - mean) * rstd * G[j].z + Bt[j].z, 0.f);
            acc[j].w += fmaxf((v[j].w - mean) * rstd * G[j].w + Bt[j].w, 0.f);
        }
    }
    #pragma unroll
    for (int j = 0; j < 4; j++) {
        const int cb = (lane + 32 * j) * 4;
        *(uint2*)(gS + (size_t)n * H_ + cb) =
            make_uint2(pkh(acc[j].x, acc[j].y), pkh(acc[j].z, acc[j].w));
    }
}

// ---------------- LN + relu of gN2r ----------------
__global__ __launch_bounds__(256)
void ln2_k(const float* CONST g, const float* CONST bt)
{
    const int tid = threadIdx.x, warp = tid >> 5, lane = tid & 31;
    const int n = blockIdx.x * 8 + warp;
    const float4* rp = (const float4*)(gN2r + (size_t)n * H_);
    float4 v[4];
    float s = 0.f, sq = 0.f;
    #pragma unroll
    for (int j = 0; j < 4; j++) {
        v[j] = rp[lane + 32 * j];
        s  += v[j].x + v[j].y + v[j].z + v[j].w;
        sq += v[j].x * v[j].x + v[j].y * v[j].y + v[j].z * v[j].z + v[j].w * v[j].w;
    }
    #pragma unroll
    for (int o = 16; o > 0; o >>= 1) {
        s  += __shfl_xor_sync(0xffffffff, s, o);
        sq += __shfl_xor_sync(0xffffffff, sq, o);
    }
    const float mean = s * (1.f / 512.f);
    const float rstd = rsqrtf(sq * (1.f / 512.f) - mean * mean + EPS);
    float4* op = (float4*)(gN2 + (size_t)n * H_);
    #pragma unroll
    for (int j = 0; j < 4; j++) {
        const int c = (lane + 32 * j) * 4;
        float4 o4;
        o4.x = fmaxf((v[j].x - mean) * rstd * g[c]     + bt[c],     0.f);
        o4.y = fmaxf((v[j].y - mean) * rstd * g[c + 1] + bt[c + 1], 0.f);
        o4.z = fmaxf((v[j].z - mean) * rstd * g[c + 2] + bt[c + 2], 0.f);
        o4.w = fmaxf((v[j].w - mean) * rstd * g[c + 3] + bt[c + 3], 0.f);
        op[lane + 32 * j] = o4;
    }
}

// ---------------- out = gN2 @ nw3 + nb3 ----------------
__global__ __launch_bounds__(256)
void n3_k(const float* CONST w3, const float* CONST b3, float* CONST out)
{
    __shared__ float xs[8][H_];
    const int r0 = blockIdx.x * 8;
    const int t = threadIdx.x;
    for (int i = t; i < 8 * H_; i += 256)
        xs[i >> 9][i & 511] = gN2[(size_t)(r0 + (i >> 9)) * H_ + (i & 511)];
    __syncthreads();
    const int lr = t >> 5, c = t & 31;
    float accv = b3[c];
    #pragma unroll 8
    for (int k = 0; k < H_; k++)
        accv = fmaf(xs[lr][k], w3[k * D_ + c], accv);
    out[(size_t)(r0 + lr) * D_ + c] = accv;
}

// ---------------- launch ----------------
extern "C" void kernel_launch(void* const* d_in, const int* in_sizes, int n_in,
                              void* d_out, int out_size)
{
    (void)in_sizes; (void)n_in; (void)out_size;
    const float* states = (const float*)d_in[0];
    const int*   action = (const int*)  d_in[1];
    const float* ew1 = (const float*)d_in[2];
    const float* eb1 = (const float*)d_in[3];
    const float* ew2 = (const float*)d_in[4];
    const float* eb2 = (const float*)d_in[5];
    const float* eg  = (const float*)d_in[6];
    const float* ebt = (const float*)d_in[7];
    const float* ew3 = (const float*)d_in[8];
    const float* eb3 = (const float*)d_in[9];
    const float* nw1 = (const float*)d_in[10];
    const float* nb1 = (const float*)d_in[11];
    const float* nw2 = (const float*)d_in[12];
    const float* nb2 = (const float*)d_in[13];
    const float* ng  = (const float*)d_in[14];
    const float* nbt = (const float*)d_in[15];
    const float* nw3 = (const float*)d_in[16];
    const float* nb3 = (const float*)d_in[17];
    float* out = (float*)d_out;

    static bool attrSet = false;
    if (!attrSet) {
        cudaFuncSetAttribute(tg<0>, cudaFuncAttributeMaxDynamicSharedMemorySize, SMEM_SZ);
        cudaFuncSetAttribute(tg<2>, cudaFuncAttributeMaxDynamicSharedMemorySize, SMEM_SZ);
        cudaFuncSetAttribute(tg<3>, cudaFuncAttributeMaxDynamicSharedMemorySize, SMEM_SZ);
        cudaFuncSetAttribute(tg<4>, cudaFuncAttributeMaxDynamicSharedMemorySize, SMEM_SZ);
        cudaFuncSetAttribute(tg<5>, cudaFuncAttributeMaxDynamicSharedMemorySize, SMEM_SZ);
        attrSet = true;
    }

    f16 *w0h, *w0l, *w2h, *w2l, *w3h, *w3l, *w4h, *w4l, *w5h, *w5l;
    f16 *st, *e, *sS, *a4, *n1;
    cudaGetSymbolAddress((void**)&w0h, gW0h); cudaGetSymbolAddress((void**)&w0l, gW0l);
    cudaGetSymbolAddress((void**)&w2h, gW2h); cudaGetSymbolAddress((void**)&w2l, gW2l);
    cudaGetSymbolAddress((void**)&w3h, gW3h); cudaGetSymbolAddress((void**)&w3l, gW3l);
    cudaGetSymbolAddress((void**)&w4h, gW4h); cudaGetSymbolAddress((void**)&w4l, gW4l);
    cudaGetSymbolAddress((void**)&w5h, gW5h); cudaGetSymbolAddress((void**)&w5l, gW5l);
    cudaGetSymbolAddress((void**)&st, gST);
    cudaGetSymbolAddress((void**)&e,  gE);
    cudaGetSymbolAddress((void**)&sS, gS);
    cudaGetSymbolAddress((void**)&a4, gA4);
    cudaGetSymbolAddress((void**)&n1, gN1);

    prep_all<<<(1097728 + 255) / 256, 256>>>(ew1, ew2, ew3, nw1, nw2);
    prep_states<<<(NN * D_ + 255) / 256, 256>>>(states);

    dim3 blk(256);
    tg<0><<<dim3(8, NN / 128), blk, SMEM_SZ>>>(st, w0h, w0l, eb1, nullptr, nullptr, 0);

    for (int s = 0; s < NSLICE; s++) {
        esplit<<<ESL * 64 / 256, 256>>>(s * ESL);
        tg<2><<<dim3(4, ESL / 128), blk, SMEM_SZ>>>(e, w2h, w2l, eb2, nullptr, nullptr, s * ESL);
        ln_sum_k<<<NSL / 8, 256>>>(eg, ebt, s * NSL);
    }

    tg<3><<<dim3(4, NN / 128), blk, SMEM_SZ>>>(sS, w3h, w3l, eb3, nullptr, nullptr, 0);
    tg<4><<<dim3(4, NN / 128), blk, SMEM_SZ>>>(a4, w4h, w4l, nb1, action, nw1, 0);
    tg<5><<<dim3(4, NN / 128), blk, SMEM_SZ>>>(n1, w5h, w5l, nb2, nullptr, nullptr, 0);
    ln2_k<<<NN / 8, 256>>>(ng, nbt);
    n3_k<<<NN / 8, 256>>>(nw3, nb3, out);
}

// round 10
// speedup vs baseline: 1.8118x; 1.0988x over previous
#include <cuda_runtime.h>
#include <cuda_fp16.h>
#include <cstdint>

#define CONST __restrict__
using f16 = __half;

static constexpr int B_  = 1024;
static constexpr int KO  = 10;
static constexpr int D_  = 32;
static constexpr int H_  = 512;
static constexpr int NN  = B_ * KO;     // 10240
static constexpr int EPN = KO - 1;      // 9
static constexpr int NE  = NN * EPN;    // 92160
static constexpr float EPS = 1e-5f;
static constexpr int K4  = 544;

static constexpr int NSLICE = 4;
static constexpr int ESL = NE / NSLICE;
static constexpr int NSL = NN / NSLICE;

// ---------------- scratch ----------------
__device__ __align__(16) f16 gST[NN * D_];
__device__ float gP[NN * H_], gQ[NN * H_];
__device__ __align__(16) f16 gE[(size_t)NE * H_];
__device__ __align__(16) f16 gH2[(size_t)NE * H_];       // fp16 hidden2 (94 MB)
__device__ __align__(16) f16 gS [NN * H_];
__device__ __align__(16) f16 gA4[NN * K4];
__device__ __align__(16) f16 gN1[NN * H_];
__device__ float gN2r[NN * H_], gN2[NN * H_];

// fp16 transposed weights [N][K]
__device__ __align__(16) f16 gW0[2 * H_ * 32];   // ew1 (P|Q merged, N=1024)
__device__ __align__(16) f16 gW2[H_ * H_];
__device__ __align__(16) f16 gW3[H_ * H_];
__device__ __align__(16) f16 gW4[H_ * K4];
__device__ __align__(16) f16 gW5[H_ * H_];

// ---------------- helpers ----------------
__device__ __forceinline__ uint32_t s2u(const void* p) {
    uint32_t a;
    asm("{ .reg .u64 t; cvta.to.shared.u64 t, %1; cvt.u32.u64 %0, t; }" : "=r"(a) : "l"(p));
    return a;
}
__device__ __forceinline__ void cp16(uint32_t s, const void* g) {
    asm volatile("cp.async.cg.shared.global [%0], [%1], 16;" :: "r"(s), "l"(g));
}
__device__ __forceinline__ void ldsm4(uint32_t* r, uint32_t a) {
    asm volatile("ldmatrix.sync.aligned.m8n8.x4.shared.b16 {%0,%1,%2,%3}, [%4];"
        : "=r"(r[0]), "=r"(r[1]), "=r"(r[2]), "=r"(r[3]) : "r"(a));
}
__device__ __forceinline__ void ldsm2(uint32_t& r0, uint32_t& r1, uint32_t a) {
    asm volatile("ldmatrix.sync.aligned.m8n8.x2.shared.b16 {%0,%1}, [%2];"
        : "=r"(r0), "=r"(r1) : "r"(a));
}
__device__ __forceinline__ void mma_f16(float* c, const uint32_t* a, uint32_t b0, uint32_t b1) {
    asm("mma.sync.aligned.m16n8k16.row.col.f32.f16.f16.f32 "
        "{%0,%1,%2,%3}, {%4,%5,%6,%7}, {%8,%9}, {%0,%1,%2,%3};\n"
        : "+f"(c[0]), "+f"(c[1]), "+f"(c[2]), "+f"(c[3])
        : "r"(a[0]), "r"(a[1]), "r"(a[2]), "r"(a[3]), "r"(b0), "r"(b1));
}
__device__ __forceinline__ uint32_t pkh(float a, float b) {
    __half2 t; t.x = __float2half_rn(a); t.y = __float2half_rn(b);
    return *(uint32_t*)&t;
}

// ---------------- weight prep (fp16, transposed) ----------------
__global__ void prep_all(const float* CONST ew1, const float* CONST ew2,
                         const float* CONST ew3, const float* CONST nw1,
                         const float* CONST nw2)
{
    int idx = blockIdx.x * 256 + threadIdx.x;
    if (idx >= 1097728) return;
    const float* src; f16* dh; int K, off, skip = 0, merged = 0;
    if      (idx < 32768)  { src = ew1; dh = gW0; K = 32;  off = 0; merged = 1; }
    else if (idx < 294912) { src = ew2; dh = gW2; K = 512; off = 32768; }
    else if (idx < 557056) { src = ew3; dh = gW3; K = 512; off = 294912; }
    else if (idx < 835584) { src = nw1; dh = gW4; K = K4;  off = 557056; skip = 1; }
    else                   { src = nw2; dh = gW5; K = 512; off = 835584; }
    int i2 = idx - off;
    int k = i2 % K, n = i2 / K;
    float v;
    if (merged) {
        int sr = (n < 512) ? k : 32 + k;
        int sn = (n < 512) ? n : n - 512;
        v = src[(size_t)sr * H_ + sn];
    } else {
        int sr = (skip && k >= 32) ? k + 4 : k;
        v = src[(size_t)sr * H_ + n];
    }
    dh[i2] = __float2half_rn(v);
}

__global__ void prep_states(const float* CONST s)
{
    int idx = blockIdx.x * 256 + threadIdx.x;
    if (idx >= NN * D_) return;
    f16 h = __float2half_rn(s[idx]);
    gST[idx] = h;
    int r = idx >> 5, c = idx & 31;
    gA4[r * K4 + c] = h;
}

// ---------------- edge A: relu(P+Q) -> fp16 plane ----------------
__global__ __launch_bounds__(256) void esplit(int edgeOff)
{
    int gi = blockIdx.x * 256 + threadIdx.x;
    int e = edgeOff + (gi >> 6);
    int cg = (gi & 63) * 8;
    int node = e / EPN;
    int jj = e - node * EPN;
    int i = node % KO;
    int j = jj + (jj >= i ? 1 : 0);
    int cn = node - i + j;

    float4 p0 = *(const float4*)(gP + (size_t)node * H_ + cg);
    float4 p1 = *(const float4*)(gP + (size_t)node * H_ + cg + 4);
    float4 q0 = *(const float4*)(gQ + (size_t)cn * H_ + cg);
    float4 q1 = *(const float4*)(gQ + (size_t)cn * H_ + cg + 4);
    f16 o[8];
    o[0] = __float2half_rn(fmaxf(p0.x + q0.x, 0.f));
    o[1] = __float2half_rn(fmaxf(p0.y + q0.y, 0.f));
    o[2] = __float2half_rn(fmaxf(p0.z + q0.z, 0.f));
    o[3] = __float2half_rn(fmaxf(p0.w + q0.w, 0.f));
    o[4] = __float2half_rn(fmaxf(p1.x + q1.x, 0.f));
    o[5] = __float2half_rn(fmaxf(p1.y + q1.y, 0.f));
    o[6] = __float2half_rn(fmaxf(p1.z + q1.z, 0.f));
    o[7] = __float2half_rn(fmaxf(p1.w + q1.w, 0.f));
    *(uint4*)(gE + (size_t)e * H_ + cg) = *(const uint4*)o;
}

// ---------------- single-term fp16 mma GEMM ----------------
static constexpr int LDP = 40;
static constexpr int SZA = 128 * LDP * 2;   // 10240 B
static constexpr int STG = 2 * SZA;         // 20480 B per stage (A, W)
static constexpr int SMEM_SZ = 2 * STG;     // 40960 B

template <int MODE>
__global__ __launch_bounds__(256, 2)
void tg(const f16* CONST A_, const f16* CONST W_,
        const float* CONST bias, const int* CONST act,
        const float* CONST nw1full, int rowOff)
{
    constexpr int KT = (MODE == 0) ? 32 : (MODE == 4 ? K4 : 512);
    constexpr int NC = KT / 32;
    extern __shared__ char smraw[];
    const uint32_t sbase = s2u(smraw);

    const int tid = threadIdx.x, warp = tid >> 5, lane = tid & 31;
    const int rowBase = rowOff + blockIdx.y * 128;
    const int colBase = blockIdx.x * 128;
    const int fr = tid >> 1, fks = (tid & 1) * 16;

    const f16* pA = A_ + (size_t)(rowBase + fr) * KT + fks;
    const f16* pW = W_ + (size_t)(colBase + fr) * KT + fks;

    const uint32_t wb = sbase + (fr * LDP + fks) * 2;
    auto ldgsts = [&](int stg, int k0) {
        const uint32_t d = wb + stg * STG;
        cp16(d,           pA + k0);  cp16(d + 16,       pA + k0 + 8);
        cp16(d + SZA,     pW + k0);  cp16(d + SZA + 16, pW + k0 + 8);
        asm volatile("cp.async.commit_group;");
    };

    const int wm = warp >> 2, wn = warp & 3;     // 2x4 warps, tile 64x32
    const int la_row = lane & 15, la_sel = lane >> 4;
    const int lb_row = lane & 7,  lb_sel = (lane >> 3) & 1;

    float acc[4][4][4];
    #pragma unroll
    for (int a = 0; a < 4; a++)
        #pragma unroll
        for (int b = 0; b < 4; b++)
            #pragma unroll
            for (int c = 0; c < 4; c++) acc[a][b][c] = 0.f;

    ldgsts(0, 0);
    for (int c = 0; c < NC; c++) {
        if (c + 1 < NC) {
            ldgsts((c + 1) & 1, (c + 1) * 32);
            asm volatile("cp.async.wait_group 1;");
        } else {
            asm volatile("cp.async.wait_group 0;");
        }
        __syncthreads();

        const uint32_t uA = sbase + (c & 1) * STG;
        const uint32_t uW = uA + SZA;
        #pragma unroll
        for (int kf = 0; kf < 2; kf++) {
            const int kb = kf * 16;
            uint32_t ah[4][4];
            #pragma unroll
            for (int mt = 0; mt < 4; mt++) {
                const uint32_t ra =
                    (uint32_t)(((wm * 64 + mt * 16 + la_row) * LDP + kb + la_sel * 8) * 2);
                ldsm4(ah[mt], uA + ra);
            }
            #pragma unroll
            for (int nt = 0; nt < 4; nt++) {
                const uint32_t rb =
                    (uint32_t)(((wn * 32 + nt * 8 + lb_row) * LDP + kb + lb_sel * 8) * 2);
                uint32_t w0, w1;
                ldsm2(w0, w1, uW + rb);
                #pragma unroll
                for (int mt = 0; mt < 4; mt++)
                    mma_f16(acc[mt][nt], ah[mt], w0, w1);
            }
        }
        __syncthreads();
    }

    // ---- epilogue ----
    const int g = lane >> 2, tg2 = (lane & 3) * 2;
    #pragma unroll
    for (int mt = 0; mt < 4; mt++) {
        const int row0 = rowBase + wm * 64 + mt * 16 + g;
        const int row1 = row0 + 8;
        int a0r = 0, a1r = 0;
        if constexpr (MODE == 4) { a0r = act[row0 / KO]; a1r = act[row1 / KO]; }
        #pragma unroll
        for (int nt = 0; nt < 4; nt++) {
            const int col = colBase + wn * 32 + nt * 8 + tg2;
            float v0 = acc[mt][nt][0], v1 = acc[mt][nt][1];
            float v2 = acc[mt][nt][2], v3 = acc[mt][nt][3];
            if constexpr (MODE == 0) {
                if (colBase < 512) {
                    float b0 = bias[col], b1 = bias[col + 1];
                    *(float2*)(gP + (size_t)row0 * H_ + col) = make_float2(v0 + b0, v1 + b1);
                    *(float2*)(gP + (size_t)row1 * H_ + col) = make_float2(v2 + b0, v3 + b1);
                } else {
                    int cq = col - 512;
                    *(float2*)(gQ + (size_t)row0 * H_ + cq) = make_float2(v0, v1);
                    *(float2*)(gQ + (size_t)row1 * H_ + cq) = make_float2(v2, v3);
                }
            }
            if constexpr (MODE == 2) {
                float b0 = bias[col], b1 = bias[col + 1];
                *(uint32_t*)(gH2 + (size_t)row0 * H_ + col) = pkh(v0 + b0, v1 + b1);
                *(uint32_t*)(gH2 + (size_t)row1 * H_ + col) = pkh(v2 + b0, v3 + b1);
            }
            if constexpr (MODE == 3) {
                float b0 = 9.f * bias[col], b1 = 9.f * bias[col + 1];
                *(uint32_t*)(gA4 + (size_t)row0 * K4 + 32 + col) = pkh(v0 + b0, v1 + b1);
                *(uint32_t*)(gA4 + (size_t)row1 * K4 + 32 + col) = pkh(v2 + b0, v3 + b1);
            }
            if constexpr (MODE == 4) {
                float b0 = bias[col], b1 = bias[col + 1];
                const float* r0p = nw1full + (size_t)(32 + a0r) * H_;
                const float* r1p = nw1full + (size_t)(32 + a1r) * H_;
                *(uint32_t*)(gN1 + (size_t)row0 * H_ + col) =
                    pkh(fmaxf(v0 + b0 + r0p[col], 0.f), fmaxf(v1 + b1 + r0p[col + 1], 0.f));
                *(uint32_t*)(gN1 + (size_t)row1 * H_ + col) =
                    pkh(fmaxf(v2 + b0 + r1p[col], 0.f), fmaxf(v3 + b1 + r1p[col + 1], 0.f));
            }
            if constexpr (MODE == 5) {
                float b0 = bias[col], b1 = bias[col + 1];
                *(float2*)(gN2r + (size_t)row0 * H_ + col) = make_float2(v0 + b0, v1 + b1);
                *(float2*)(gN2r + (size_t)row1 * H_ + col) = make_float2(v2 + b0, v3 + b1);
            }
        }
    }
}

// ---------------- LN + relu + 9-row sum over fp16 gH2 -> fp16 S ----------------
__global__ __launch_bounds__(256)
void ln_sum_k(const float* CONST g, const float* CONST bt, int nodeOff)
{
    const int tid = threadIdx.x, warp = tid >> 5, lane = tid & 31;
    const int n = nodeOff + blockIdx.x * 8 + warp;

    float G[16], Bt[16], acc[16];
    #pragma unroll
    for (int j = 0; j < 2; j++) {
        const int cb = (lane + 32 * j) * 8;
        #pragma unroll
        for (int u = 0; u < 8; u++) {
            G[j * 8 + u] = g[cb + u];
            Bt[j * 8 + u] = bt[cb + u];
            acc[j * 8 + u] = 0.f;
        }
    }

    for (int e = 0; e < EPN; e++) {
        const f16* rp = gH2 + (size_t)(n * EPN + e) * H_;
        float v[16];
        float s = 0.f, sq = 0.f;
        #pragma unroll
        for (int j = 0; j < 2; j++) {
            uint4 raw = *(const uint4*)(rp + (lane + 32 * j) * 8);
            const __half2* h2 = (const __half2*)&raw;
            #pragma unroll
            for (int p = 0; p < 4; p++) {
                float2 f2 = __half22float2(h2[p]);
                v[j * 8 + p * 2]     = f2.x;
                v[j * 8 + p * 2 + 1] = f2.y;
            }
        }
        #pragma unroll
        for (int u = 0; u < 16; u++) { s += v[u]; sq += v[u] * v[u]; }
        #pragma unroll
        for (int o = 16; o > 0; o >>= 1) {
            s  += __shfl_xor_sync(0xffffffff, s, o);
            sq += __shfl_xor_sync(0xffffffff, sq, o);
        }
        const float mean = s * (1.f / 512.f);
        const float rstd = rsqrtf(sq * (1.f / 512.f) - mean * mean + EPS);
        #pragma unroll
        for (int u = 0; u < 16; u++)
            acc[u] += fmaxf((v[u] - mean) * rstd * G[u] + Bt[u], 0.f);
    }

    #pragma unroll
    for (int j = 0; j < 2; j++) {
        const int cb = (lane + 32 * j) * 8;
        uint4 o4;
        o4.x = pkh(acc[j * 8 + 0], acc[j * 8 + 1]);
        o4.y = pkh(acc[j * 8 + 2], acc[j * 8 + 3]);
        o4.z = pkh(acc[j * 8 + 4], acc[j * 8 + 5]);
        o4.w = pkh(acc[j * 8 + 6], acc[j * 8 + 7]);
        *(uint4*)(gS + (size_t)n * H_ + cb) = o4;
    }
}

// ---------------- LN + relu of gN2r ----------------
__global__ __launch_bounds__(256)
void ln2_k(const float* CONST g, const float* CONST bt)
{
    const int tid = threadIdx.x, warp = tid >> 5, lane = tid & 31;
    const int n = blockIdx.x * 8 + warp;
    const float4* rp = (const float4*)(gN2r + (size_t)n * H_);
    float4 v[4];
    float s = 0.f, sq = 0.f;
    #pragma unroll
    for (int j = 0; j < 4; j++) {
        v[j] = rp[lane + 32 * j];
        s  += v[j].x + v[j].y + v[j].z + v[j].w;
        sq += v[j].x * v[j].x + v[j].y * v[j].y + v[j].z * v[j].z + v[j].w * v[j].w;
    }
    #pragma unroll
    for (int o = 16; o > 0; o >>= 1) {
        s  += __shfl_xor_sync(0xffffffff, s, o);
        sq += __shfl_xor_sync(0xffffffff, sq, o);
    }
    const float mean = s * (1.f / 512.f);
    const float rstd = rsqrtf(sq * (1.f / 512.f) - mean * mean + EPS);
    float4* op = (float4*)(gN2 + (size_t)n * H_);
    #pragma unroll
    for (int j = 0; j < 4; j++) {
        const int c = (lane + 32 * j) * 4;
        float4 o4;
        o4.x = fmaxf((v[j].x - mean) * rstd * g[c]     + bt[c],     0.f);
        o4.y = fmaxf((v[j].y - mean) * rstd * g[c + 1] + bt[c + 1], 0.f);
        o4.z = fmaxf((v[j].z - mean) * rstd * g[c + 2] + bt[c + 2], 0.f);
        o4.w = fmaxf((v[j].w - mean) * rstd * g[c + 3] + bt[c + 3], 0.f);
        op[lane + 32 * j] = o4;
    }
}

// ---------------- out = gN2 @ nw3 + nb3 ----------------
__global__ __launch_bounds__(256)
void n3_k(const float* CONST w3, const float* CONST b3, float* CONST out)
{
    __shared__ float xs[8][H_];
    const int r0 = blockIdx.x * 8;
    const int t = threadIdx.x;
    for (int i = t; i < 8 * H_; i += 256)
        xs[i >> 9][i & 511] = gN2[(size_t)(r0 + (i >> 9)) * H_ + (i & 511)];
    __syncthreads();
    const int lr = t >> 5, c = t & 31;
    float accv = b3[c];
    #pragma unroll 8
    for (int k = 0; k < H_; k++)
        accv = fmaf(xs[lr][k], w3[k * D_ + c], accv);
    out[(size_t)(r0 + lr) * D_ + c] = accv;
}

// ---------------- launch ----------------
extern "C" void kernel_launch(void* const* d_in, const int* in_sizes, int n_in,
                              void* d_out, int out_size)
{
    (void)in_sizes; (void)n_in; (void)out_size;
    const float* states = (const float*)d_in[0];
    const int*   action = (const int*)  d_in[1];
    const float* ew1 = (const float*)d_in[2];
    const float* eb1 = (const float*)d_in[3];
    const float* ew2 = (const float*)d_in[4];
    const float* eb2 = (const float*)d_in[5];
    const float* eg  = (const float*)d_in[6];
    const float* ebt = (const float*)d_in[7];
    const float* ew3 = (const float*)d_in[8];
    const float* eb3 = (const float*)d_in[9];
    const float* nw1 = (const float*)d_in[10];
    const float* nb1 = (const float*)d_in[11];
    const float* nw2 = (const float*)d_in[12];
    const float* nb2 = (const float*)d_in[13];
    const float* ng  = (const float*)d_in[14];
    const float* nbt = (const float*)d_in[15];
    const float* nw3 = (const float*)d_in[16];
    const float* nb3 = (const float*)d_in[17];
    float* out = (float*)d_out;

    static bool attrSet = false;
    if (!attrSet) {
        cudaFuncSetAttribute(tg<0>, cudaFuncAttributeMaxDynamicSharedMemorySize, SMEM_SZ);
        cudaFuncSetAttribute(tg<2>, cudaFuncAttributeMaxDynamicSharedMemorySize, SMEM_SZ);
        cudaFuncSetAttribute(tg<3>, cudaFuncAttributeMaxDynamicSharedMemorySize, SMEM_SZ);
        cudaFuncSetAttribute(tg<4>, cudaFuncAttributeMaxDynamicSharedMemorySize, SMEM_SZ);
        cudaFuncSetAttribute(tg<5>, cudaFuncAttributeMaxDynamicSharedMemorySize, SMEM_SZ);
        attrSet = true;
    }

    f16 *w0, *w2, *w3, *w4, *w5, *st, *e, *sS, *a4, *n1;
    cudaGetSymbolAddress((void**)&w0, gW0);
    cudaGetSymbolAddress((void**)&w2, gW2);
    cudaGetSymbolAddress((void**)&w3, gW3);
    cudaGetSymbolAddress((void**)&w4, gW4);
    cudaGetSymbolAddress((void**)&w5, gW5);
    cudaGetSymbolAddress((void**)&st, gST);
    cudaGetSymbolAddress((void**)&e,  gE);
    cudaGetSymbolAddress((void**)&sS, gS);
    cudaGetSymbolAddress((void**)&a4, gA4);
    cudaGetSymbolAddress((void**)&n1, gN1);

    prep_all<<<(1097728 + 255) / 256, 256>>>(ew1, ew2, ew3, nw1, nw2);
    prep_states<<<(NN * D_ + 255) / 256, 256>>>(states);

    dim3 blk(256);
    tg<0><<<dim3(8, NN / 128), blk, SMEM_SZ>>>(st, w0, eb1, nullptr, nullptr, 0);

    for (int s = 0; s < NSLICE; s++) {
        esplit<<<ESL * 64 / 256, 256>>>(s * ESL);
        tg<2><<<dim3(4, ESL / 128), blk, SMEM_SZ>>>(e, w2, eb2, nullptr, nullptr, s * ESL);
        ln_sum_k<<<NSL / 8, 256>>>(eg, ebt, s * NSL);
    }

    tg<3><<<dim3(4, NN / 128), blk, SMEM_SZ>>>(sS, w3, eb3, nullptr, nullptr, 0);
    tg<4><<<dim3(4, NN / 128), blk, SMEM_SZ>>>(a4, w4, nb1, action, nw1, 0);
    tg<5><<<dim3(4, NN / 128), blk, SMEM_SZ>>>(n1, w5, nb2, nullptr, nullptr, 0);
    ln2_k<<<NN / 8, 256>>>(ng, nbt);
    n3_k<<<NN / 8, 256>>>(nw3, nb3, out);
}